// round 4
// baseline (speedup 1.0000x reference)
#include <cuda_runtime.h>
#include <math.h>

#define N_NODES 260000
#define N_EDGES 8320000
#define N_GRAPHS 10000
#define GN 26

// Scratch (device globals: no allocation allowed).
// xs: per-node [sum_x(4), deg(1), pad(3)]  stride 8 floats (16B-aligned for v4 red)
__device__ float4 g_xs4[N_NODES * 2];     // 8.3 MB
// z: per-node h1@W2^T, 11 used + 1 pad, stride 12 floats
__device__ float4 g_z4[N_NODES * 3];      // 12.5 MB
// agg2: scatter target for layer 2, stride 12 floats
__device__ float4 g_agg4[N_NODES * 3];    // 12.5 MB
// per-graph pooled sums [G][4]
__device__ float4 g_g4[N_GRAPHS];         // 160 KB

__device__ __forceinline__ void red4(float* p, float a, float b, float c, float d) {
    asm volatile("red.global.add.v4.f32 [%0], {%1,%2,%3,%4};"
                 :: "l"(__cvta_generic_to_global(p)), "f"(a), "f"(b), "f"(c), "f"(d)
                 : "memory");
}
__device__ __forceinline__ void red1(float* p, float a) {
    asm volatile("red.global.add.f32 [%0], %1;"
                 :: "l"(__cvta_generic_to_global(p)), "f"(a)
                 : "memory");
}

// ---------------- K0: zero scratch ----------------
__global__ void zero_kernel() {
    int i = blockIdx.x * blockDim.x + threadIdx.x;
    float4 z = make_float4(0.f, 0.f, 0.f, 0.f);
    if (i < N_NODES * 2) g_xs4[i] = z;
    if (i < N_NODES * 3) g_agg4[i] = z;
    if (i < N_GRAPHS)    g_g4[i] = z;
}

// ---------------- K1: edge pass 1 — scatter raw x + degree ----------------
__global__ void edge1_kernel(const int* __restrict__ ei, const float4* __restrict__ x) {
    int e = blockIdx.x * blockDim.x + threadIdx.x;
    if (e >= N_EDGES) return;
    int r = __ldg(&ei[e]);
    int c = __ldg(&ei[N_EDGES + e]);
    float4 v = __ldg(&x[r]);
    float* p = (float*)&g_xs4[c * 2];
    red4(p, v.x, v.y, v.z, v.w);
    red1(p + 4, 1.0f);
}

// ---------------- K2: node pass 1 — h1 = tanh(...), z = h1 @ W2^T ----------------
__global__ void node1_kernel(const float4* __restrict__ x,
                             const float* __restrict__ W1,
                             const float* __restrict__ b1,
                             const float* __restrict__ W2) {
    __shared__ float sW1[26 * 4];
    __shared__ float sb1[26];
    __shared__ float sW2[11 * 26];
    int t = threadIdx.x;
    for (int i = t; i < 26 * 4; i += blockDim.x) sW1[i] = W1[i];
    for (int i = t; i < 26; i += blockDim.x)     sb1[i] = b1[i];
    for (int i = t; i < 11 * 26; i += blockDim.x) sW2[i] = W2[i];
    __syncthreads();

    int i = blockIdx.x * blockDim.x + t;
    if (i >= N_NODES) return;

    float4 s  = g_xs4[i * 2];
    float  cnt = ((const float*)&g_xs4[i * 2])[4];
    float4 xi = __ldg(&x[i]);
    float t0 = s.x + xi.x, t1 = s.y + xi.y, t2 = s.z + xi.z, t3 = s.w + xi.w;
    float c1 = cnt + 1.0f;

    float h[26];
#pragma unroll
    for (int j = 0; j < 26; j++) {
        float a = fmaf(sW1[j * 4 + 0], t0,
                  fmaf(sW1[j * 4 + 1], t1,
                  fmaf(sW1[j * 4 + 2], t2,
                  fmaf(sW1[j * 4 + 3], t3, c1 * sb1[j]))));
        h[j] = tanhf(a);
    }

    float z[12];
#pragma unroll
    for (int k = 0; k < 11; k++) {
        float a = 0.f;
#pragma unroll
        for (int j = 0; j < 26; j++) a = fmaf(sW2[k * 26 + j], h[j], a);
        z[k] = a;
    }
    z[11] = 0.f;

    float4* zp = &g_z4[i * 3];
    zp[0] = make_float4(z[0], z[1], z[2],  z[3]);
    zp[1] = make_float4(z[4], z[5], z[6],  z[7]);
    zp[2] = make_float4(z[8], z[9], z[10], z[11]);
}

// ---------------- K3: edge pass 2 — scatter z (11-dim, padded to 12) ----------------
__global__ void edge2_kernel(const int* __restrict__ ei) {
    int e = blockIdx.x * blockDim.x + threadIdx.x;
    if (e >= N_EDGES) return;
    int r = __ldg(&ei[e]);
    int c = __ldg(&ei[N_EDGES + e]);
    const float4* zp = &g_z4[r * 3];
    float4 a = __ldg(&zp[0]);
    float4 b = __ldg(&zp[1]);
    float4 d = __ldg(&zp[2]);
    float* p = (float*)&g_agg4[c * 3];
    red4(p,     a.x, a.y, a.z, a.w);
    red4(p + 4, b.x, b.y, b.z, b.w);
    red4(p + 8, d.x, d.y, d.z, d.w);   // lane 11 is the 0-pad, harmless
}

// ---------------- K4: node pass 2 — tanh, maxpool, graph-sum scatter ----------------
__global__ void node2_kernel(const float* __restrict__ b2) {
    __shared__ float sb2[11];
    int t = threadIdx.x;
    if (t < 11) sb2[t] = b2[t];
    __syncthreads();

    int i = blockIdx.x * blockDim.x + t;
    if (i >= N_NODES) return;

    float c1 = ((const float*)&g_xs4[i * 2])[4] + 1.0f;
    const float4* ap = &g_agg4[i * 3];
    const float4* zp = &g_z4[i * 3];
    float v[11];
    float4 a0 = ap[0], a1 = ap[1], a2 = ap[2];
    float4 z0 = zp[0], z1 = zp[1], z2 = zp[2];
    float av[12] = {a0.x, a0.y, a0.z, a0.w, a1.x, a1.y, a1.z, a1.w, a2.x, a2.y, a2.z, a2.w};
    float zv[12] = {z0.x, z0.y, z0.z, z0.w, z1.x, z1.y, z1.z, z1.w, z2.x, z2.y, z2.z, z2.w};
#pragma unroll
    for (int k = 0; k < 11; k++)
        v[k] = tanhf(av[k] + zv[k] + c1 * sb2[k]);

    // MaxPool1d(3, stride 3, pad-left 1): windows (-inf,v0,v1),(v2,v3,v4),(v5,v6,v7),(v8,v9,v10)
    float p0 = fmaxf(v[0], v[1]);
    float p1 = fmaxf(fmaxf(v[2], v[3]), v[4]);
    float p2 = fmaxf(fmaxf(v[5], v[6]), v[7]);
    float p3 = fmaxf(fmaxf(v[8], v[9]), v[10]);

    int gi = i / GN;
    red4((float*)&g_g4[gi], p0, p1, p2, p3);
}

// ---------------- K5: per-graph linear + softmax ----------------
__global__ void final_kernel(const float* __restrict__ Wl,
                             const float* __restrict__ bl,
                             float* __restrict__ out) {
    int g = blockIdx.x * blockDim.x + threadIdx.x;
    if (g >= N_GRAPHS) return;
    float4 gv = g_g4[g];
    float o0 = fmaf(Wl[0], gv.x, fmaf(Wl[1], gv.y, fmaf(Wl[2], gv.z, fmaf(Wl[3], gv.w, bl[0]))));
    float o1 = fmaf(Wl[4], gv.x, fmaf(Wl[5], gv.y, fmaf(Wl[6], gv.z, fmaf(Wl[7], gv.w, bl[1]))));
    float m = fmaxf(o0, o1);
    float e0 = expf(o0 - m), e1 = expf(o1 - m);
    float inv = 1.0f / (e0 + e1);
    out[g * 2 + 0] = e0 * inv;
    out[g * 2 + 1] = e1 * inv;
}

extern "C" void kernel_launch(void* const* d_in, const int* in_sizes, int n_in,
                              void* d_out, int out_size) {
    const float4* x  = (const float4*)d_in[0];   // [260000,4] f32
    const int*    ei = (const int*)d_in[1];      // [2, 8320000] i32
    const float*  W1 = (const float*)d_in[2];    // [26,4]
    const float*  b1 = (const float*)d_in[3];    // [26]
    const float*  W2 = (const float*)d_in[4];    // [11,26]
    const float*  b2 = (const float*)d_in[5];    // [11]
    const float*  Wl = (const float*)d_in[6];    // [2,4]
    const float*  bl = (const float*)d_in[7];    // [2]
    float* out = (float*)d_out;                  // [10000,2]

    const int T = 256;
    zero_kernel<<<(N_NODES * 3 + T - 1) / T, T>>>();
    edge1_kernel<<<(N_EDGES + T - 1) / T, T>>>(ei, x);
    node1_kernel<<<(N_NODES + T - 1) / T, T>>>(x, W1, b1, W2);
    edge2_kernel<<<(N_EDGES + T - 1) / T, T>>>(ei);
    node2_kernel<<<(N_NODES + T - 1) / T, T>>>(b2);
    final_kernel<<<(N_GRAPHS + T - 1) / T, T>>>(Wl, bl, out);
}